// round 15
// baseline (speedup 1.0000x reference)
#include <cuda_runtime.h>
#include <cuda_fp16.h>

// LightGCN pull-form with dinv folded into storage:
//   z_l := dinv ⊙ x_l  (fp16);  pull: t[c] = sum z_l[src]  (pure sum)
//   z_{l+1}[c] = dinv[c]^2 * t ;  out = 0.25*(x0 + sqd*(z1+z2) + dinv*t3)
// CSR (src-only) rebuilt every call, degree padded to EVEN with dummy src = NN
// (permanently-zero feature row) -> branch-free pull loop.
// Atomic split: deg pass records per-edge slot (returning atomic, coalesced pos
// write); fill pass is atomic-free scatter.

static constexpr int    NU = 100000;
static constexpr int    NI = 50000;
static constexpr int    NN = NU + NI;        // 150000
static constexpr int    D  = 128;
static constexpr int    NE = 2000000;
static constexpr size_t ND = (size_t)NN * D; // 19.2M elems

static constexpr int SCAN_B   = 1024;
static constexpr int NSCANBLK = (NN + SCAN_B - 1) / SCAN_B;  // 147
static_assert(NSCANBLK <= 256, "bsum scan assumes <=256 blocks");

// ---- static scratch ----
__device__ __half g_xh[3][ND + D];   // z0, z1, z2 fp16; extra zero row at index NN
__device__ float  g_dinv[NN];
__device__ float  g_sqd[NN];         // sqrt(deg), 0 if deg==0
__device__ int    g_deg[NN];         // zeroed by scan3 each call
__device__ int    g_rowptr[NN + 1];  // padded offsets (even)
__device__ int    g_pos[NE];         // per-edge slot within its dst segment
__device__ int    g_bsum[256];
__device__ int    g_edge[NE + NN];   // src only, grouped by dst, even-padded

// ---- helpers ----
__device__ __forceinline__ float4 h4_to_f4(uint2 v) {
    float2 f0 = __half22float2(*reinterpret_cast<__half2*>(&v.x));
    float2 f1 = __half22float2(*reinterpret_cast<__half2*>(&v.y));
    return make_float4(f0.x, f0.y, f1.x, f1.y);
}
__device__ __forceinline__ uint2 f4_to_h4(float4 v) {
    __half2 h0 = __floats2half2_rn(v.x, v.y);
    __half2 h1 = __floats2half2_rn(v.z, v.w);
    uint2 o;
    o.x = *reinterpret_cast<unsigned*>(&h0);
    o.y = *reinterpret_cast<unsigned*>(&h1);
    return o;
}

// ---------------- degree + per-edge slot ----------------
__global__ void deg_kernel(const int* __restrict__ col, int E) {
    int e = blockIdx.x * blockDim.x + threadIdx.x;
    if (e < E) {
        unsigned c = (unsigned)col[e];
        int p = 0;
        if (c < (unsigned)NN) p = atomicAdd(&g_deg[c], 1);
        g_pos[e] = p;
    }
}

// ---------------- scan part 1 over EVEN-padded degree (+ dinv & sqrt(deg)) ----------------
__global__ void scan1_kernel() {
    __shared__ int s[SCAN_B];
    int tid = threadIdx.x;
    int i = blockIdx.x * SCAN_B + tid;
    int d = (i < NN) ? g_deg[i] : 0;
    int v = (d + 1) & ~1;                      // padded degree (even)
    if (i < NN) {
        g_dinv[i] = (d > 0) ? rsqrtf((float)d) : 0.0f;
        g_sqd[i]  = sqrtf((float)d);
    }
    s[tid] = v;
    __syncthreads();
    for (int off = 1; off < SCAN_B; off <<= 1) {
        int t = (tid >= off) ? s[tid - off] : 0;
        __syncthreads();
        s[tid] += t;
        __syncthreads();
    }
    if (i < NN) g_rowptr[i] = s[tid] - v;      // block-local exclusive
    if (tid == SCAN_B - 1) g_bsum[blockIdx.x] = s[tid];
}

// bsum scan folded in; finalizes rowptr, writes pad slots, self-zeroes g_deg.
__global__ void scan3_kernel() {
    __shared__ int s[256];
    int tid = threadIdx.x;
    int v = (tid < NSCANBLK) ? g_bsum[tid] : 0;
    s[tid] = v;
    __syncthreads();
    for (int off = 1; off < 256; off <<= 1) {
        int t = (tid >= off) ? s[tid - off] : 0;
        __syncthreads();
        s[tid] += t;
        __syncthreads();
    }
    __shared__ int excl[256];
    if (tid < 256) excl[tid] = s[tid] - v;
    __syncthreads();

    int i = blockIdx.x * blockDim.x + tid;
    if (i < NN) {
        int d = g_deg[i];
        int rp = g_rowptr[i] + excl[i / SCAN_B];
        g_rowptr[i] = rp;
        if (d & 1) g_edge[rp + d] = NN;        // single pad slot
        if (i == NN - 1) g_rowptr[NN] = rp + ((d + 1) & ~1);
        g_deg[i] = 0;                          // ready for next replay
    }
}

// ---------------- CSR fill (atomic-free) ----------------
__global__ void fill_kernel(const int* __restrict__ row,
                            const int* __restrict__ col, int E) {
    int e = blockIdx.x * blockDim.x + threadIdx.x;
    if (e < E) {
        unsigned r = (unsigned)row[e];
        unsigned c = (unsigned)col[e];
        if (r < (unsigned)NN && c < (unsigned)NN) {
            g_edge[g_rowptr[c] + g_pos[e]] = (int)r;
        }
    }
}

// ---------------- z0 = fp16( dinv * concat(user, item) ) ----------------
__global__ void cvt0_kernel(const float* __restrict__ user_w,
                            const float* __restrict__ item_w) {
    size_t i = (size_t)blockIdx.x * blockDim.x + threadIdx.x; // float4 granule
    const size_t n4  = ND / 4;
    const size_t nu4 = (size_t)NU * (D / 4);
    if (i < n4) {
        float4 v = (i < nu4) ? ((const float4*)user_w)[i]
                             : ((const float4*)item_w)[i - nu4];
        float dn = g_dinv[i >> 5];   // 32 granules per node
        v.x *= dn; v.y *= dn; v.z *= dn; v.w *= dn;
        ((uint2*)g_xh[0])[i] = f4_to_h4(v);
    }
}

// ---------------- pull (champion R11 structure, untouched) ----------------
template <bool FINAL>
__global__ void __launch_bounds__(256) pull_kernel(
    int lin, int lout,
    const float* __restrict__ user_w, const float* __restrict__ item_w,
    float* __restrict__ out)
{
    int node = (int)((blockIdx.x * (size_t)blockDim.x + threadIdx.x) >> 5);
    int lane = threadIdx.x & 31;
    if (node >= NN) return;

    int beg = g_rowptr[node];
    int end = g_rowptr[node + 1];

    int half = lane >> 4;   // which edge of the pair
    int sub  = lane & 15;   // 16B slice within the 256B row

    const uint4* __restrict__ xin = (const uint4*)g_xh[lin]; // 16 uint4 per row

    float a0 = 0.f, a1 = 0.f, a2 = 0.f, a3 = 0.f;
    float a4 = 0.f, a5 = 0.f, a6 = 0.f, a7 = 0.f;

    #pragma unroll 4
    for (int j = beg; j < end; j += 2) {
        int src = g_edge[j + half];
        uint4 r = xin[(size_t)src * 16 + sub];
        float2 f0 = __half22float2(*reinterpret_cast<__half2*>(&r.x));
        float2 f1 = __half22float2(*reinterpret_cast<__half2*>(&r.y));
        float2 f2 = __half22float2(*reinterpret_cast<__half2*>(&r.z));
        float2 f3 = __half22float2(*reinterpret_cast<__half2*>(&r.w));
        a0 += f0.x; a1 += f0.y;
        a2 += f1.x; a3 += f1.y;
        a4 += f2.x; a5 += f2.y;
        a6 += f3.x; a7 += f3.y;
    }

    a0 += __shfl_xor_sync(0xFFFFFFFFu, a0, 16);
    a1 += __shfl_xor_sync(0xFFFFFFFFu, a1, 16);
    a2 += __shfl_xor_sync(0xFFFFFFFFu, a2, 16);
    a3 += __shfl_xor_sync(0xFFFFFFFFu, a3, 16);
    a4 += __shfl_xor_sync(0xFFFFFFFFu, a4, 16);
    a5 += __shfl_xor_sync(0xFFFFFFFFu, a5, 16);
    a6 += __shfl_xor_sync(0xFFFFFFFFu, a6, 16);
    a7 += __shfl_xor_sync(0xFFFFFFFFu, a7, 16);

    float b0 = half ? a4 : a0;
    float b1 = half ? a5 : a1;
    float b2 = half ? a6 : a2;
    float b3 = half ? a7 : a3;
    size_t idx = (size_t)node * 32 + sub * 2 + half;   // float4 / uint2 granule

    float dn = g_dinv[node];

    if (FINAL) {
        float sd = g_sqd[node];
        float4 x0 = (node < NU)
            ? ((const float4*)user_w)[idx]
            : ((const float4*)item_w)[idx - (size_t)NU * 32];
        float4 z1 = h4_to_f4(((const uint2*)g_xh[1])[idx]);
        float4 z2 = h4_to_f4(((const uint2*)g_xh[2])[idx]);
        float4 o;
        o.x = 0.25f * (x0.x + sd * (z1.x + z2.x) + dn * b0);
        o.y = 0.25f * (x0.y + sd * (z1.y + z2.y) + dn * b1);
        o.z = 0.25f * (x0.z + sd * (z1.z + z2.z) + dn * b2);
        o.w = 0.25f * (x0.w + sd * (z1.w + z2.w) + dn * b3);
        ((float4*)out)[idx] = o;
    } else {
        float s = dn * dn;   // z_out = dinv^2 * t
        ((uint2*)g_xh[lout])[idx] =
            f4_to_h4(make_float4(s * b0, s * b1, s * b2, s * b3));
    }
}

extern "C" void kernel_launch(void* const* d_in, const int* in_sizes, int n_in,
                              void* d_out, int out_size)
{
    const int*   edge_index = (const int*)d_in[0];   // [2, E] int32
    const float* user_w     = (const float*)d_in[1]; // [NU, D]
    const float* item_w     = (const float*)d_in[2]; // [NI, D]
    float*       out        = (float*)d_out;         // [NN, D]

    const int E = in_sizes[0] / 2;
    const int* row = edge_index;
    const int* col = edge_index + E;

    const int TB = 256;
    const int n4_blocks = (int)((ND / 4 + TB - 1) / TB);
    const int nn_blocks = (NN + TB - 1) / TB;
    const int e_blocks  = (E + TB - 1) / TB;
    const int pw_blocks = (NN + (TB / 32) - 1) / (TB / 32);

    // degree + per-edge slot (g_deg zeroed by previous replay's scan3)
    deg_kernel<<<e_blocks, TB>>>(col, E);
    scan1_kernel<<<NSCANBLK, SCAN_B>>>();
    scan3_kernel<<<nn_blocks, TB>>>();     // bsum scan + pads + deg zero
    fill_kernel<<<e_blocks, TB>>>(row, col, E);

    // z0 = dinv * x0 in fp16 (needs dinv from scan1)
    cvt0_kernel<<<n4_blocks, TB>>>(user_w, item_w);

    // layers 1,2 into fp16 z-buffers; layer 3 fused with the final mean
    pull_kernel<false><<<pw_blocks, TB>>>(0, 1, user_w, item_w, out);
    pull_kernel<false><<<pw_blocks, TB>>>(1, 2, user_w, item_w, out);
    pull_kernel<true ><<<pw_blocks, TB>>>(2, 0, user_w, item_w, out);
}

// round 16
// speedup vs baseline: 1.0478x; 1.0478x over previous
#include <cuda_runtime.h>
#include <cuda_fp16.h>

// LightGCN pull-form with dinv folded into storage:
//   z_l := dinv ⊙ x_l  (fp16);  pull: t[c] = sum z_l[src]  (pure sum)
//   z_{l+1}[c] = dinv[c]^2 * t ;  out = 0.25*(x0 + sqd*(z1+z2) + dinv*t3)
// CSR (src-only) rebuilt every call, degree padded to EVEN with dummy src = NN
// (permanently-zero feature row) -> branch-free pull loop.
// Build chain: deg (int2-vectorized, returning atomic + pos) -> scan1 -> scan3
// -> fused fill+cvt (atomic-free scatter + fp16 convert in one kernel).

static constexpr int    NU = 100000;
static constexpr int    NI = 50000;
static constexpr int    NN = NU + NI;        // 150000
static constexpr int    D  = 128;
static constexpr int    NE = 2000000;
static constexpr size_t ND = (size_t)NN * D; // 19.2M elems

static constexpr int SCAN_B   = 1024;
static constexpr int NSCANBLK = (NN + SCAN_B - 1) / SCAN_B;  // 147
static_assert(NSCANBLK <= 256, "bsum scan assumes <=256 blocks");

// ---- static scratch ----
__device__ __half g_xh[3][ND + D];   // z0, z1, z2 fp16; extra zero row at index NN
__device__ float  g_dinv[NN];
__device__ float  g_sqd[NN];         // sqrt(deg), 0 if deg==0
__device__ int    g_deg[NN];         // zeroed by scan3 each call
__device__ int    g_rowptr[NN + 1];  // padded offsets (even)
__device__ int    g_pos[NE];         // per-edge slot within its dst segment
__device__ int    g_bsum[256];
__device__ int    g_edge[NE + NN];   // src only, grouped by dst, even-padded

// ---- helpers ----
__device__ __forceinline__ float4 h4_to_f4(uint2 v) {
    float2 f0 = __half22float2(*reinterpret_cast<__half2*>(&v.x));
    float2 f1 = __half22float2(*reinterpret_cast<__half2*>(&v.y));
    return make_float4(f0.x, f0.y, f1.x, f1.y);
}
__device__ __forceinline__ uint2 f4_to_h4(float4 v) {
    __half2 h0 = __floats2half2_rn(v.x, v.y);
    __half2 h1 = __floats2half2_rn(v.z, v.w);
    uint2 o;
    o.x = *reinterpret_cast<unsigned*>(&h0);
    o.y = *reinterpret_cast<unsigned*>(&h1);
    return o;
}

// ---------------- degree + per-edge slot (2 edges per thread) ----------------
__global__ void deg_kernel(const int* __restrict__ col, int E) {
    int t = blockIdx.x * blockDim.x + threadIdx.x;
    int e = t * 2;
    if (e + 1 < E) {
        int2 c2 = *(const int2*)&col[e];
        int p0 = 0, p1 = 0;
        if ((unsigned)c2.x < (unsigned)NN) p0 = atomicAdd(&g_deg[c2.x], 1);
        if ((unsigned)c2.y < (unsigned)NN) p1 = atomicAdd(&g_deg[c2.y], 1);
        *(int2*)&g_pos[e] = make_int2(p0, p1);
    } else if (e < E) {
        unsigned c = (unsigned)col[e];
        int p = 0;
        if (c < (unsigned)NN) p = atomicAdd(&g_deg[c], 1);
        g_pos[e] = p;
    }
}

// ---------------- scan part 1 over EVEN-padded degree (+ dinv & sqrt(deg)) ----------------
__global__ void scan1_kernel() {
    __shared__ int s[SCAN_B];
    int tid = threadIdx.x;
    int i = blockIdx.x * SCAN_B + tid;
    int d = (i < NN) ? g_deg[i] : 0;
    int v = (d + 1) & ~1;                      // padded degree (even)
    if (i < NN) {
        g_dinv[i] = (d > 0) ? rsqrtf((float)d) : 0.0f;
        g_sqd[i]  = sqrtf((float)d);
    }
    s[tid] = v;
    __syncthreads();
    for (int off = 1; off < SCAN_B; off <<= 1) {
        int t = (tid >= off) ? s[tid - off] : 0;
        __syncthreads();
        s[tid] += t;
        __syncthreads();
    }
    if (i < NN) g_rowptr[i] = s[tid] - v;      // block-local exclusive
    if (tid == SCAN_B - 1) g_bsum[blockIdx.x] = s[tid];
}

// bsum scan folded in; finalizes rowptr, writes pad slots, self-zeroes g_deg.
__global__ void scan3_kernel() {
    __shared__ int s[256];
    int tid = threadIdx.x;
    int v = (tid < NSCANBLK) ? g_bsum[tid] : 0;
    s[tid] = v;
    __syncthreads();
    for (int off = 1; off < 256; off <<= 1) {
        int t = (tid >= off) ? s[tid - off] : 0;
        __syncthreads();
        s[tid] += t;
        __syncthreads();
    }
    __shared__ int excl[256];
    if (tid < 256) excl[tid] = s[tid] - v;
    __syncthreads();

    int i = blockIdx.x * blockDim.x + tid;
    if (i < NN) {
        int d = g_deg[i];
        int rp = g_rowptr[i] + excl[i / SCAN_B];
        g_rowptr[i] = rp;
        if (d & 1) g_edge[rp + d] = NN;        // single pad slot
        if (i == NN - 1) g_rowptr[NN] = rp + ((d + 1) & ~1);
        g_deg[i] = 0;                          // ready for next replay
    }
}

// ---------------- fused fill (atomic-free) + z0 convert ----------------
// Phase 1: one edge per thread -> scatter src into CSR slot.
// Phase 2: grid-stride over feature granules -> z0 = fp16(dinv * x0).
__global__ void fill_cvt_kernel(const int* __restrict__ row,
                                const int* __restrict__ col, int E,
                                const float* __restrict__ user_w,
                                const float* __restrict__ item_w) {
    int e = blockIdx.x * blockDim.x + threadIdx.x;
    if (e < E) {
        unsigned r = (unsigned)row[e];
        unsigned c = (unsigned)col[e];
        if (r < (unsigned)NN && c < (unsigned)NN) {
            g_edge[g_rowptr[c] + g_pos[e]] = (int)r;
        }
    }
    // convert phase (independent of the scatter above)
    const size_t n4     = ND / 4;
    const size_t nu4    = (size_t)NU * (D / 4);
    const size_t stride = (size_t)gridDim.x * blockDim.x;
    for (size_t i = (size_t)blockIdx.x * blockDim.x + threadIdx.x; i < n4; i += stride) {
        float4 v = (i < nu4) ? ((const float4*)user_w)[i]
                             : ((const float4*)item_w)[i - nu4];
        float dn = g_dinv[i >> 5];   // 32 granules per node
        v.x *= dn; v.y *= dn; v.z *= dn; v.w *= dn;
        ((uint2*)g_xh[0])[i] = f4_to_h4(v);
    }
}

// ---------------- pull (champion structure, untouched) ----------------
template <bool FINAL>
__global__ void __launch_bounds__(256) pull_kernel(
    int lin, int lout,
    const float* __restrict__ user_w, const float* __restrict__ item_w,
    float* __restrict__ out)
{
    int node = (int)((blockIdx.x * (size_t)blockDim.x + threadIdx.x) >> 5);
    int lane = threadIdx.x & 31;
    if (node >= NN) return;

    int beg = g_rowptr[node];
    int end = g_rowptr[node + 1];

    int half = lane >> 4;   // which edge of the pair
    int sub  = lane & 15;   // 16B slice within the 256B row

    const uint4* __restrict__ xin = (const uint4*)g_xh[lin]; // 16 uint4 per row

    float a0 = 0.f, a1 = 0.f, a2 = 0.f, a3 = 0.f;
    float a4 = 0.f, a5 = 0.f, a6 = 0.f, a7 = 0.f;

    #pragma unroll 4
    for (int j = beg; j < end; j += 2) {
        int src = g_edge[j + half];
        uint4 r = xin[(size_t)src * 16 + sub];
        float2 f0 = __half22float2(*reinterpret_cast<__half2*>(&r.x));
        float2 f1 = __half22float2(*reinterpret_cast<__half2*>(&r.y));
        float2 f2 = __half22float2(*reinterpret_cast<__half2*>(&r.z));
        float2 f3 = __half22float2(*reinterpret_cast<__half2*>(&r.w));
        a0 += f0.x; a1 += f0.y;
        a2 += f1.x; a3 += f1.y;
        a4 += f2.x; a5 += f2.y;
        a6 += f3.x; a7 += f3.y;
    }

    a0 += __shfl_xor_sync(0xFFFFFFFFu, a0, 16);
    a1 += __shfl_xor_sync(0xFFFFFFFFu, a1, 16);
    a2 += __shfl_xor_sync(0xFFFFFFFFu, a2, 16);
    a3 += __shfl_xor_sync(0xFFFFFFFFu, a3, 16);
    a4 += __shfl_xor_sync(0xFFFFFFFFu, a4, 16);
    a5 += __shfl_xor_sync(0xFFFFFFFFu, a5, 16);
    a6 += __shfl_xor_sync(0xFFFFFFFFu, a6, 16);
    a7 += __shfl_xor_sync(0xFFFFFFFFu, a7, 16);

    float b0 = half ? a4 : a0;
    float b1 = half ? a5 : a1;
    float b2 = half ? a6 : a2;
    float b3 = half ? a7 : a3;
    size_t idx = (size_t)node * 32 + sub * 2 + half;   // float4 / uint2 granule

    float dn = g_dinv[node];

    if (FINAL) {
        float sd = g_sqd[node];
        float4 x0 = (node < NU)
            ? ((const float4*)user_w)[idx]
            : ((const float4*)item_w)[idx - (size_t)NU * 32];
        float4 z1 = h4_to_f4(((const uint2*)g_xh[1])[idx]);
        float4 z2 = h4_to_f4(((const uint2*)g_xh[2])[idx]);
        float4 o;
        o.x = 0.25f * (x0.x + sd * (z1.x + z2.x) + dn * b0);
        o.y = 0.25f * (x0.y + sd * (z1.y + z2.y) + dn * b1);
        o.z = 0.25f * (x0.z + sd * (z1.z + z2.z) + dn * b2);
        o.w = 0.25f * (x0.w + sd * (z1.w + z2.w) + dn * b3);
        ((float4*)out)[idx] = o;
    } else {
        float s = dn * dn;   // z_out = dinv^2 * t
        ((uint2*)g_xh[lout])[idx] =
            f4_to_h4(make_float4(s * b0, s * b1, s * b2, s * b3));
    }
}

extern "C" void kernel_launch(void* const* d_in, const int* in_sizes, int n_in,
                              void* d_out, int out_size)
{
    const int*   edge_index = (const int*)d_in[0];   // [2, E] int32
    const float* user_w     = (const float*)d_in[1]; // [NU, D]
    const float* item_w     = (const float*)d_in[2]; // [NI, D]
    float*       out        = (float*)d_out;         // [NN, D]

    const int E = in_sizes[0] / 2;
    const int* row = edge_index;
    const int* col = edge_index + E;

    const int TB = 256;
    const int nn_blocks = (NN + TB - 1) / TB;
    const int e_blocks  = (E + TB - 1) / TB;
    const int e2_blocks = ((E + 1) / 2 + TB - 1) / TB;
    const int pw_blocks = (NN + (TB / 32) - 1) / (TB / 32);

    // degree + per-edge slot (g_deg zeroed by previous replay's scan3)
    deg_kernel<<<e2_blocks, TB>>>(col, E);
    scan1_kernel<<<NSCANBLK, SCAN_B>>>();
    scan3_kernel<<<nn_blocks, TB>>>();     // bsum scan + pads + deg zero
    fill_cvt_kernel<<<e_blocks, TB>>>(row, col, E, user_w, item_w);

    // layers 1,2 into fp16 z-buffers; layer 3 fused with the final mean
    pull_kernel<false><<<pw_blocks, TB>>>(0, 1, user_w, item_w, out);
    pull_kernel<false><<<pw_blocks, TB>>>(1, 2, user_w, item_w, out);
    pull_kernel<true ><<<pw_blocks, TB>>>(2, 0, user_w, item_w, out);
}